// round 15
// baseline (speedup 1.0000x reference)
#include <cuda_runtime.h>
#include <cuda_bf16.h>
#include <cstdint>

// ---------------- problem constants ----------------
#define B_SZ   16
#define CIN    512
#define L_IN   4000
#define KW     16
#define L_OUT  31992              // 3999*8
#define TPB    256
#define TSTRIDE 15                // y-rows produced per warp
#define TILES_PS 267              // ceil(3999/15)
#define BLK_PS  34                // ceil(267/8 warps)

// dynamic smem: ws_hi u32[CIN*KW] (32 KB) + ws_lo u16/bf16[CIN*KW] (16 KB)
#define SMEM_BYTES (CIN * KW * 4 + CIN * KW * 2)   // 49152

#define MMA_TF32(d, a0, a1, a2, a3, b0, b1)                                  \
    asm volatile("mma.sync.aligned.m16n8k8.row.col.f32.tf32.tf32.f32 "       \
                 "{%0,%1,%2,%3}, {%4,%5,%6,%7}, {%8,%9}, {%0,%1,%2,%3};"     \
                 : "+f"(d[0]), "+f"(d[1]), "+f"(d[2]), "+f"(d[3])            \
                 : "r"(a0), "r"(a1), "r"(a2), "r"(a3), "r"(b0), "r"(b1))

// ---------------------------------------------------------------------------
// Single fused kernel.
// Per warp-tile (b, m0 = tile*15): accumulate D[16m x 16k] = x^T W over 64
// cin-chunks of 8 (hi pass + bf16-residual lo pass -> W numerically exact).
// Epilogue: y[8m+p] = z[m][p+8] + z[m+1][p] via intra-warp shfl, direct STG.
// A fragments (x) load straight from gmem: a0 = x[cin=cb*8+l][m0+r] etc.
// (l = lane&3, r = lane>>2) -- every 32B sector fully used.
// B fragments (W) from smem: b0 = W[cb*8+l][8h+r], b1 = +4 cin rows.
// ---------------------------------------------------------------------------
extern "C" __global__ void __launch_bounds__(TPB, 4)
fused_kernel(const float* __restrict__ x,
             const float* __restrict__ t60s,
             const float* __restrict__ kw,
             float* __restrict__ out)
{
    extern __shared__ __align__(16) unsigned char smem[];
    uint32_t*       ws_hi = (uint32_t*)smem;                  // [CIN*KW]
    unsigned short* ws_lo = (unsigned short*)(smem + CIN * KW * 4);

    const int tid = threadIdx.x;
    const int b   = blockIdx.y;
    const int idxb = (int)rintf(t60s[b & 7] * 100.0f) - 10;
    const float* wsrc = kw + (size_t)idxb * (CIN * KW);

    // W split: hi = tf32_rna(w), lo = bf16(w - hi). hi+lo ~ 18+ mantissa bits.
    for (int i = tid; i < CIN * KW; i += TPB) {
        float w = wsrc[i];
        uint32_t hb;
        asm("cvt.rna.tf32.f32 %0, %1;" : "=r"(hb) : "f"(w));
        float lo = w - __uint_as_float(hb);
        __nv_bfloat16 lb = __float2bfloat16(lo);
        ws_hi[i] = hb;
        ws_lo[i] = *(unsigned short*)&lb;
    }
    __syncthreads();

    const int wid  = tid >> 5;
    const int lane = tid & 31;
    const int tile = blockIdx.x * 8 + wid;
    if (tile >= TILES_PS) return;                 // after the only barrier

    const int m0 = tile * TSTRIDE;
    const int r  = lane >> 2;                     // m row within fragment
    const int l  = lane & 3;                      // cin within chunk
    const int c0 = min(m0 + r,     L_IN - 1);     // clamped x columns
    const int c1 = min(m0 + r + 8, L_IN - 1);

    const float* p0 = x + (size_t)b * CIN * L_IN + (size_t)l * L_IN;
    const int bo = l * 16 + r;                    // B-frag word offset in chunk

    float acc0[4] = {0.f, 0.f, 0.f, 0.f};         // k 0..7  (front half)
    float acc1[4] = {0.f, 0.f, 0.f, 0.f};         // k 8..15 (back half)

#pragma unroll 4
    for (int cb = 0; cb < CIN / 8; ++cb) {
        const float* q = p0 + (size_t)cb * 8 * L_IN;
        float f0 = q[c0];
        float f1 = q[c1];
        float f2 = q[4 * L_IN + c0];
        float f3 = q[4 * L_IN + c1];
        uint32_t a0, a1, a2, a3;
        asm("cvt.rna.tf32.f32 %0, %1;" : "=r"(a0) : "f"(f0));
        asm("cvt.rna.tf32.f32 %0, %1;" : "=r"(a1) : "f"(f1));
        asm("cvt.rna.tf32.f32 %0, %1;" : "=r"(a2) : "f"(f2));
        asm("cvt.rna.tf32.f32 %0, %1;" : "=r"(a3) : "f"(f3));

        const int base = cb * 128 + bo;
        // hi pass
        {
            uint32_t b0 = ws_hi[base],      b1 = ws_hi[base + 64];
            MMA_TF32(acc0, a0, a1, a2, a3, b0, b1);
            b0 = ws_hi[base + 8];           b1 = ws_hi[base + 72];
            MMA_TF32(acc1, a0, a1, a2, a3, b0, b1);
        }
        // lo pass (bf16 residual; bits<<16 is exact f32 -> valid tf32)
        {
            uint32_t b0 = (uint32_t)ws_lo[base]      << 16;
            uint32_t b1 = (uint32_t)ws_lo[base + 64] << 16;
            MMA_TF32(acc0, a0, a1, a2, a3, b0, b1);
            b0 = (uint32_t)ws_lo[base + 8]  << 16;
            b1 = (uint32_t)ws_lo[base + 72] << 16;
            MMA_TF32(acc1, a0, a1, a2, a3, b0, b1);
        }
    }

    // ---- epilogue: y[8m+p] = z[m][p+8] + z[m+1][p] ----
    // acc*[0],[1]: row m0+r,   cols 2l, 2l+1 (within half)
    // acc*[2],[3]: row m0+r+8, cols 2l, 2l+1
    const unsigned FULL = 0xffffffffu;
    float fa0 = __shfl_sync(FULL, acc0[0], (lane + 4) & 31);  // z[m0+r+1][2l]   (r<7)
    float fa1 = __shfl_sync(FULL, acc0[1], (lane + 4) & 31);
    float fb0 = __shfl_sync(FULL, acc0[2], (lane + 4) & 31);  // r<7: z[m0+r+9][2l]; r==7: z[m0+8][2l]
    float fb1 = __shfl_sync(FULL, acc0[3], (lane + 4) & 31);

    float* ob = out + (size_t)b * L_OUT;

    // group A: y row m0 + r
    {
        const int row = m0 + r;
        if (row <= L_IN - 2) {
            float n0 = (r < 7) ? fa0 : fb0;
            float n1 = (r < 7) ? fa1 : fb1;
            float2 v = make_float2(acc1[0] + n0, acc1[1] + n1);
            *(float2*)(ob + (size_t)row * 8 + 2 * l) = v;
        }
    }
    // group B: y row m0 + 8 + r (only r < 7; neighbor = z[m0+r+9][2l] = fb)
    {
        const int row = m0 + 8 + r;
        if (r < 7 && row <= L_IN - 2) {
            float2 v = make_float2(acc1[2] + fb0, acc1[3] + fb1);
            *(float2*)(ob + (size_t)row * 8 + 2 * l) = v;
        }
    }
}

// ---------------------------------------------------------------------------
extern "C" void kernel_launch(void* const* d_in, const int* in_sizes, int n_in,
                              void* d_out, int out_size)
{
    const float* x    = (const float*)d_in[0];   // (16, 512, 4000) f32
    const float* t60s = (const float*)d_in[1];   // (8,)            f32
    const float* kw   = (const float*)d_in[2];   // (41, 512, 1, 16) f32
    float*       out  = (float*)d_out;           // (16, 1, 31992)  f32

    cudaFuncSetAttribute(fused_kernel,
                         cudaFuncAttributeMaxDynamicSharedMemorySize,
                         SMEM_BYTES);

    dim3 grid(BLK_PS, B_SZ);                     // 34 x 16 = 544 blocks
    fused_kernel<<<grid, TPB, SMEM_BYTES>>>(x, t60s, kw, out);
}

// round 17
// speedup vs baseline: 1.1550x; 1.1550x over previous
#include <cuda_runtime.h>
#include <cuda_bf16.h>
#include <cstdint>

// ---------------- problem constants ----------------
#define B_SZ   16
#define CIN    512
#define L_IN   4000
#define KW     16
#define L_OUT  31992             // 3999*8
#define TPB    256
#define BLOCK_MROWS 252          // y-rows produced per block
#define NBLK   16                // ceil(3999/252)
#define WSTRIDE 24               // W smem cin stride (words) -> conflict-free
#define XROW    264              // xs row stride (words)     -> conflict-free

// smem layout (bytes)
#define OFF_WHI 0
#define OFF_WLO (CIN * WSTRIDE * 4)                 // 49152
#define OFF_XS  (OFF_WLO + CIN * WSTRIDE * 2)       // 73728
#define XS_BUF_BYTES (16 * XROW * 4)                // 16896
#define OFF_EX  (OFF_XS + 2 * XS_BUF_BYTES)        // 107520
#define SMEM_TOTAL (OFF_EX + 8 * 8 * 4)            // 107776

#define MMA_TF32(d, a0, a1, a2, a3, b0, b1)                                  \
    asm volatile("mma.sync.aligned.m16n8k8.row.col.f32.tf32.tf32.f32 "       \
                 "{%0,%1,%2,%3}, {%4,%5,%6,%7}, {%8,%9}, {%0,%1,%2,%3};"     \
                 : "+f"(d[0]), "+f"(d[1]), "+f"(d[2]), "+f"(d[3])            \
                 : "r"(a0), "r"(a1), "r"(a2), "r"(a3), "r"(b0), "r"(b1))

#define CVT_TF32(u, f) asm("cvt.rna.tf32.f32 %0, %1;" : "=r"(u) : "f"(f))

// ---------------------------------------------------------------------------
// One fused kernel. Block (mb, b): covers z columns [252*mb, 252*mb+256),
// produces y rows [252*mb, 252*mb+252). 8 warps x 32 m each, 2 fragment
// subtiles of 16 m. x staged gmem->smem by cp.async (double-buffered groups
// of 16 cin rows); W split hi(tf32)+lo(bf16) in smem (exact). Epilogue emits
// y[8m+p] = z[m][p+8] + z[m+1][p] via shfl + one smem column exchange.
// ---------------------------------------------------------------------------
extern "C" __global__ void __launch_bounds__(TPB, 2)
fused_kernel(const float* __restrict__ x,
             const float* __restrict__ t60s,
             const float* __restrict__ kw,
             float* __restrict__ out)
{
    extern __shared__ __align__(16) unsigned char smem[];
    uint32_t sbase;
    asm("{ .reg .u64 t; cvta.to.shared.u64 t, %1; cvt.u32.u64 %0, t; }"
        : "=r"(sbase) : "l"(smem));
    uint32_t*       ws_hi = (uint32_t*)(smem + OFF_WHI);
    unsigned short* ws_lo = (unsigned short*)(smem + OFF_WLO);
    float*          exs   = (float*)(smem + OFF_EX);

    const int tid  = threadIdx.x;
    const int b    = blockIdx.y;
    const int mblk = blockIdx.x * BLOCK_MROWS;

    // ---- W build: hi = tf32_rna(w), lo = bf16(w - hi)  (W numerically exact)
    const int idxb = (int)rintf(t60s[b & 7] * 100.0f) - 10;
    const float* wsrc = kw + (size_t)idxb * (CIN * KW);
    for (int i = tid; i < CIN * KW; i += TPB) {
        const int cin = i >> 4, k = i & 15;
        float w = wsrc[i];
        uint32_t hb; CVT_TF32(hb, w);
        float lo = w - __uint_as_float(hb);
        __nv_bfloat16 lb = __float2bfloat16(lo);
        ws_hi[cin * WSTRIDE + k] = hb;
        ws_lo[cin * WSTRIDE + k] = *(unsigned short*)&lb;
    }
    // (first use is after the g=0 wait + __syncthreads)

    // ---- staging geometry (fixed per thread) ----
    const int row0   = tid >> 6;                    // 0..3
    const int quad   = tid & 63;                    // 16B quad within 256 m
    const int colc   = min(mblk + quad * 4, L_IN - 4);   // clamped float4 col
    const uint32_t dst0 = sbase + OFF_XS + (uint32_t)row0 * (XROW * 4) + quad * 16;
    const float* xb = x + (size_t)b * CIN * L_IN;

    auto stage = [&](int g, int buf) {
        const float* s0 = xb + (size_t)(16 * g + row0) * L_IN + colc;
        uint32_t d0 = dst0 + (uint32_t)buf * XS_BUF_BYTES;
#pragma unroll
        for (int j = 0; j < 4; ++j) {
            const float* s = s0 + (size_t)(4 * j) * L_IN;
            uint32_t d = d0 + (uint32_t)(4 * j) * (XROW * 4);
            asm volatile("cp.async.cg.shared.global [%0], [%1], 16;"
                         :: "r"(d), "l"(s) : "memory");
        }
        asm volatile("cp.async.commit_group;" ::: "memory");
    };

    stage(0, 0);
    stage(1, 1);

    const int wid  = tid >> 5;
    const int lane = tid & 31;
    const int r    = lane >> 2;                    // fragment row
    const int l    = lane & 3;                     // fragment col (cin in chunk)

    // accumulators: [subtile][front k0-7 | back k8-15]
    float aF0[4] = {0,0,0,0}, aB0[4] = {0,0,0,0};  // subtile 0 (m 32w..+15)
    float aF1[4] = {0,0,0,0}, aB1[4] = {0,0,0,0};  // subtile 1 (m 32w+16..+31)

    const int mloc = 32 * wid;                     // warp's local m base

#pragma unroll 1
    for (int g = 0; g < 32; ++g) {
        if (g >= 30) asm volatile("cp.async.wait_group 0;" ::: "memory");
        else         asm volatile("cp.async.wait_group 1;" ::: "memory");
        __syncthreads();

        const float* xsf = (const float*)(smem + OFF_XS + (g & 1) * XS_BUF_BYTES);

#pragma unroll
        for (int cc = 0; cc < 2; ++cc) {
            const int c0 = 16 * g + 8 * cc;        // global cin base of chunk

            // W fragments (shared by both subtiles), conflict-free LDS
            const int wb = (c0 + l) * WSTRIDE + r;
            uint32_t bf0h = ws_hi[wb];
            uint32_t bf1h = ws_hi[wb + 4 * WSTRIDE];
            uint32_t bb0h = ws_hi[wb + 8];
            uint32_t bb1h = ws_hi[wb + 4 * WSTRIDE + 8];
            uint32_t bf0l = (uint32_t)ws_lo[wb] << 16;
            uint32_t bf1l = (uint32_t)ws_lo[wb + 4 * WSTRIDE] << 16;
            uint32_t bb0l = (uint32_t)ws_lo[wb + 8] << 16;
            uint32_t bb1l = (uint32_t)ws_lo[wb + 4 * WSTRIDE + 8] << 16;

            const int ab = (8 * cc + l) * XROW + mloc + r;

            // subtile 0
            {
                float f0 = xsf[ab], f1 = xsf[ab + 8];
                float f2 = xsf[ab + 4 * XROW], f3 = xsf[ab + 4 * XROW + 8];
                uint32_t a0, a1, a2, a3;
                CVT_TF32(a0, f0); CVT_TF32(a1, f1);
                CVT_TF32(a2, f2); CVT_TF32(a3, f3);
                MMA_TF32(aF0, a0, a1, a2, a3, bf0h, bf1h);
                MMA_TF32(aB0, a0, a1, a2, a3, bb0h, bb1h);
                MMA_TF32(aF0, a0, a1, a2, a3, bf0l, bf1l);
                MMA_TF32(aB0, a0, a1, a2, a3, bb0l, bb1l);
            }
            // subtile 1 (m + 16)
            {
                float f0 = xsf[ab + 16], f1 = xsf[ab + 24];
                float f2 = xsf[ab + 4 * XROW + 16], f3 = xsf[ab + 4 * XROW + 24];
                uint32_t a0, a1, a2, a3;
                CVT_TF32(a0, f0); CVT_TF32(a1, f1);
                CVT_TF32(a2, f2); CVT_TF32(a3, f3);
                MMA_TF32(aF1, a0, a1, a2, a3, bf0h, bf1h);
                MMA_TF32(aB1, a0, a1, a2, a3, bb0h, bb1h);
                MMA_TF32(aF1, a0, a1, a2, a3, bf0l, bf1l);
                MMA_TF32(aB1, a0, a1, a2, a3, bb0l, bb1l);
            }
        }
        __syncthreads();
        if (g + 2 < 32) stage(g + 2, g & 1);
    }

    // ---- cross-warp column exchange: z[32(w+1)][0..7] front = warp w+1 sub0 F r=0
    if (lane < 4) {
        exs[wid * 8 + 2 * l]     = aF0[0];
        exs[wid * 8 + 2 * l + 1] = aF0[1];
    }
    __syncthreads();
    float ex0 = 0.f, ex1 = 0.f;
    if (wid < 7) {
        ex0 = exs[(wid + 1) * 8 + 2 * l];
        ex1 = exs[(wid + 1) * 8 + 2 * l + 1];
    }

    // ---- epilogue: y[8m+p] = z[m][p+8](back, own row) + z[m+1][p](front, next)
    const unsigned FULL = 0xffffffffu;
    float* ob = out + (size_t)b * L_OUT;
    const int src = (lane + 4) & 31;

    // subtile 0: external neighbor = subtile 1 front r=0 (via shfl)
    {
        float fa0 = __shfl_sync(FULL, aF0[0], src), fa1 = __shfl_sync(FULL, aF0[1], src);
        float fb0 = __shfl_sync(FULL, aF0[2], src), fb1 = __shfl_sync(FULL, aF0[3], src);
        float e0  = __shfl_sync(FULL, aF1[0], src), e1  = __shfl_sync(FULL, aF1[1], src);

        const int rowA = mblk + mloc + r;
        if (rowA <= L_IN - 2) {
            float n0 = (r < 7) ? fa0 : fb0, n1 = (r < 7) ? fa1 : fb1;
            *(float2*)(ob + (size_t)rowA * 8 + 2 * l) =
                make_float2(aB0[0] + n0, aB0[1] + n1);
        }
        const int rowB = rowA + 8;
        if (rowB <= L_IN - 2) {                     // local < 252 always (max 247)
            float n0 = (r < 7) ? fb0 : e0, n1 = (r < 7) ? fb1 : e1;
            *(float2*)(ob + (size_t)rowB * 8 + 2 * l) =
                make_float2(aB0[2] + n0, aB0[3] + n1);
        }
    }
    // subtile 1: external neighbor = next warp's column (exs)
    {
        float fa0 = __shfl_sync(FULL, aF1[0], src), fa1 = __shfl_sync(FULL, aF1[1], src);
        float fb0 = __shfl_sync(FULL, aF1[2], src), fb1 = __shfl_sync(FULL, aF1[3], src);

        const int rowA = mblk + mloc + 16 + r;
        if (rowA <= L_IN - 2) {                     // local < 252 always (max 247)
            float n0 = (r < 7) ? fa0 : fb0, n1 = (r < 7) ? fa1 : fb1;
            *(float2*)(ob + (size_t)rowA * 8 + 2 * l) =
                make_float2(aB1[0] + n0, aB1[1] + n1);
        }
        const int rowB = rowA + 8;
        const int lrowB = mloc + 24 + r;            // warp7 r=7 -> 255: not ours
        if (lrowB < BLOCK_MROWS && rowB <= L_IN - 2) {
            float n0 = (r < 7) ? fb0 : ex0, n1 = (r < 7) ? fb1 : ex1;
            *(float2*)(ob + (size_t)rowB * 8 + 2 * l) =
                make_float2(aB1[2] + n0, aB1[3] + n1);
        }
    }
}

// ---------------------------------------------------------------------------
extern "C" void kernel_launch(void* const* d_in, const int* in_sizes, int n_in,
                              void* d_out, int out_size)
{
    const float* x    = (const float*)d_in[0];   // (16, 512, 4000) f32
    const float* t60s = (const float*)d_in[1];   // (8,)            f32
    const float* kw   = (const float*)d_in[2];   // (41, 512, 1, 16) f32
    float*       out  = (float*)d_out;           // (16, 1, 31992)  f32

    cudaFuncSetAttribute(fused_kernel,
                         cudaFuncAttributeMaxDynamicSharedMemorySize,
                         SMEM_TOTAL);

    dim3 grid(NBLK, B_SZ);                       // 16 x 16 = 256 blocks
    fused_kernel<<<grid, TPB, SMEM_TOTAL>>>(x, t60s, kw, out);
}